// round 6
// baseline (speedup 1.0000x reference)
#include <cuda_runtime.h>
#include <math.h>
#include <stdint.h>

#define B_ 128
#define L_ 512
#define N_ 1023
#define T_ 511
#define D_ 256
#define C_ 511
#define EPS_ 1e-6f

// 128*1023*256 floats = 134 MB scratch (allocs are forbidden -> device global)
__device__ float g_vec[(size_t)B_ * N_ * D_];

__device__ __forceinline__ uint32_t smem_to_u32(const void* p) {
    uint32_t a;
    asm("{ .reg .u64 t; cvta.to.shared.u64 t, %1; cvt.u32.u64 %0, t; }"
        : "=r"(a) : "l"(p));
    return a;
}

// ---------------------------------------------------------------------------
// Zero the node-vector buffer
// ---------------------------------------------------------------------------
__global__ void zero_kernel() {
    size_t total4 = (size_t)B_ * N_ * D_ / 4;
    float4* p = reinterpret_cast<float4*>(g_vec);
    float4 z = make_float4(0.f, 0.f, 0.f, 0.f);
    for (size_t i = (size_t)blockIdx.x * blockDim.x + threadIdx.x; i < total4;
         i += (size_t)gridDim.x * blockDim.x)
        p[i] = z;
}

// ---------------------------------------------------------------------------
// Scatter normalized embedding rows into g_vec. One warp per leaf.
// ---------------------------------------------------------------------------
__global__ void embed_kernel(const int* __restrict__ leaf_id,
                             const int* __restrict__ mask,
                             const float* __restrict__ emb) {
    int leaf = blockIdx.x * 8 + (threadIdx.x >> 5);
    int lane = threadIdx.x & 31;
    if (leaf >= B_ * L_) return;
    if (mask[leaf] == 0) return;
    int b = leaf / L_;
    int node = leaf_id[2 * leaf + 0];
    int vid  = leaf_id[2 * leaf + 1];
    if ((unsigned)node >= (unsigned)N_) return;
    const float4* src = reinterpret_cast<const float4*>(emb + (size_t)vid * D_);
    float4 v0 = src[lane];
    float4 v1 = src[lane + 32];
    float ss = v0.x * v0.x + v0.y * v0.y + v0.z * v0.z + v0.w * v0.w
             + v1.x * v1.x + v1.y * v1.y + v1.z * v1.z + v1.w * v1.w;
#pragma unroll
    for (int o = 16; o > 0; o >>= 1) ss += __shfl_xor_sync(0xffffffffu, ss, o);
    float inv = 1.f / (sqrtf(ss) + EPS_);
    v0.x *= inv; v0.y *= inv; v0.z *= inv; v0.w *= inv;
    v1.x *= inv; v1.y *= inv; v1.z *= inv; v1.w *= inv;
    float4* dst = reinterpret_cast<float4*>(g_vec + ((size_t)b * N_ + node) * D_);
    dst[lane]      = v0;
    dst[lane + 32] = v1;
}

// ---------------------------------------------------------------------------
// Sequential tree composition. One block per batch.
// Packed f32x2 circular correlation:
//   thread (t = tid&63, g = tid>>6) computes outputs k = 4t..4t+3 over
//   j in [64g, 64g+64), pairing j with j+1:
//     acc_i (f32x2) += (a[j], a[j+1]) * (b[j+k+i], b[j+k+i+1])
//   and sums the two lanes at the end. Odd-start b pairs come 16B-aligned
//   from a shifted copy sb1[i] = b[i+1].
// ---------------------------------------------------------------------------
__global__ void __launch_bounds__(256) compose_kernel(const int* __restrict__ comp) {
    __shared__ int sinfo[T_ * 4];
    __shared__ __align__(16) float sa[D_];
    __shared__ __align__(16) float sb0[512];   // sb0[i] = b[i % 256]
    __shared__ __align__(16) float sb1[512];   // sb1[i] = b[(i+1) % 256]
    __shared__ float pt[4][320];
    __shared__ float red[8];

    int b = blockIdx.x;
    int tid = threadIdx.x;
    float* v = g_vec + (size_t)b * N_ * D_;

    for (int i = tid; i < T_ * 4; i += 256)
        sinfo[i] = comp[(size_t)b * T_ * 4 + i];
    __syncthreads();

    const int t  = tid & 63;
    const int g  = tid >> 6;
    const int j0 = g * 64;
    const int sP = j0 + t * 4;                   // pair-base float index
    const int ftid = tid + (tid >> 2);
    const int m1 = (tid == 0) ? 255 : (tid - 1); // sb1 write index

    const uint32_t saA  = smem_to_u32(sa)  + (uint32_t)j0 * 4;
    const uint32_t eA   = smem_to_u32(sb0) + (uint32_t)sP * 4;
    const uint32_t oA   = smem_to_u32(sb1) + (uint32_t)sP * 4;

    for (int ts = 0; ts < T_; ++ts) {
        int typ = sinfo[4 * ts + 0];
        int p   = sinfo[4 * ts + 1];
        int l   = sinfo[4 * ts + 2];
        int r   = sinfo[4 * ts + 3];
        if (typ == 1) {
            // column-private: no sync needed
            v[(size_t)p * D_ + tid] = v[(size_t)l * D_ + tid];
        } else if (typ == 2) {
            float av = v[(size_t)l * D_ + tid];
            float bv = v[(size_t)r * D_ + tid];
            sa[tid] = av;
            sb0[tid] = bv;  sb0[tid + 256] = bv;
            sb1[m1]  = bv;  sb1[m1 + 256]  = bv;
            __syncthreads();

            unsigned long long acc0 = 0ull, acc1 = 0ull, acc2 = 0ull, acc3 = 0ull;
            unsigned long long E0, E1, O0, O1;
            asm("ld.shared.v2.u64 {%0,%1}, [%2];" : "=l"(E0), "=l"(E1) : "r"(eA));
            asm("ld.shared.v2.u64 {%0,%1}, [%2];" : "=l"(O0), "=l"(O1) : "r"(oA));
#pragma unroll
            for (int u = 0; u < 16; ++u) {
                unsigned long long pe0, pe1, En0, En1, On0, On1;
                asm("ld.shared.v2.u64 {%0,%1}, [%2];"
                    : "=l"(pe0), "=l"(pe1) : "r"(saA + 16u * u));
                asm("ld.shared.v2.u64 {%0,%1}, [%2];"
                    : "=l"(En0), "=l"(En1) : "r"(eA + 16u * (u + 1)));
                asm("ld.shared.v2.u64 {%0,%1}, [%2];"
                    : "=l"(On0), "=l"(On1) : "r"(oA + 16u * (u + 1)));
                // step j (pe0 = (a[j], a[j+1])):
                asm("fma.rn.f32x2 %0, %1, %2, %0;" : "+l"(acc0) : "l"(pe0), "l"(E0));
                asm("fma.rn.f32x2 %0, %1, %2, %0;" : "+l"(acc1) : "l"(pe0), "l"(O0));
                asm("fma.rn.f32x2 %0, %1, %2, %0;" : "+l"(acc2) : "l"(pe0), "l"(E1));
                asm("fma.rn.f32x2 %0, %1, %2, %0;" : "+l"(acc3) : "l"(pe0), "l"(O1));
                // step j+2 (pe1 = (a[j+2], a[j+3])):
                asm("fma.rn.f32x2 %0, %1, %2, %0;" : "+l"(acc0) : "l"(pe1), "l"(E1));
                asm("fma.rn.f32x2 %0, %1, %2, %0;" : "+l"(acc1) : "l"(pe1), "l"(O1));
                asm("fma.rn.f32x2 %0, %1, %2, %0;" : "+l"(acc2) : "l"(pe1), "l"(En0));
                asm("fma.rn.f32x2 %0, %1, %2, %0;" : "+l"(acc3) : "l"(pe1), "l"(On0));
                E0 = En0; E1 = En1; O0 = On0; O1 = On1;
            }
            float lo, hi, c0, c1, c2, c3;
            asm("mov.b64 {%0,%1}, %2;" : "=f"(lo), "=f"(hi) : "l"(acc0)); c0 = lo + hi;
            asm("mov.b64 {%0,%1}, %2;" : "=f"(lo), "=f"(hi) : "l"(acc1)); c1 = lo + hi;
            asm("mov.b64 {%0,%1}, %2;" : "=f"(lo), "=f"(hi) : "l"(acc2)); c2 = lo + hi;
            asm("mov.b64 {%0,%1}, %2;" : "=f"(lo), "=f"(hi) : "l"(acc3)); c3 = lo + hi;

            pt[g][5 * t + 0] = c0;
            pt[g][5 * t + 1] = c1;
            pt[g][5 * t + 2] = c2;
            pt[g][5 * t + 3] = c3;
            __syncthreads();

            float tot = pt[0][ftid] + pt[1][ftid] + pt[2][ftid] + pt[3][ftid];
            float ss = tot * tot;
#pragma unroll
            for (int o = 16; o > 0; o >>= 1)
                ss += __shfl_xor_sync(0xffffffffu, ss, o);
            if ((tid & 31) == 0) red[tid >> 5] = ss;
            __syncthreads();
            float tss = red[0] + red[1] + red[2] + red[3]
                      + red[4] + red[5] + red[6] + red[7];
            v[(size_t)p * D_ + tid] = tot / (sqrtf(tss) + EPS_);
            __syncthreads();
        }
        // typ == 0: exact no-op
    }
}

// ---------------------------------------------------------------------------
// tf32 mma.sync GEMM: out[m, c] = sum_d A[m, d] * W[c, d] + bias[c]
// BM=128, BN=64, BK=32, 256 threads (8 warps: 4 along M x 2 along N).
// Warp tile 32x32 = 2 x 4 m16n8k8 tiles. cp.async double-buffered smem,
// stride 36 floats. 3 CTAs/SM (occupancy for latency hiding).
// ---------------------------------------------------------------------------
#define GS 36                      // smem row stride in floats
#define A_ST (128 * GS)
#define B_ST (64 * GS)
#define STAGE_F (A_ST + B_ST)      // 6912 floats = 27648 B per stage

__device__ __forceinline__ void cp16(uint32_t dst, const void* src) {
    asm volatile("cp.async.ca.shared.global [%0], [%1], 16;"
                 :: "r"(dst), "l"(src) : "memory");
}
__device__ __forceinline__ void cp16z(uint32_t dst, const void* src, int srcsz) {
    asm volatile("cp.async.ca.shared.global [%0], [%1], 16, %2;"
                 :: "r"(dst), "l"(src), "r"(srcsz) : "memory");
}
__device__ __forceinline__ void cp_commit() {
    asm volatile("cp.async.commit_group;" ::: "memory");
}
__device__ __forceinline__ void cp_wait0() {
    asm volatile("cp.async.wait_group 0;" ::: "memory");
}
__device__ __forceinline__ void mma_tf32(float* d, const uint32_t* a,
                                         uint32_t b0, uint32_t b1) {
    asm volatile(
        "mma.sync.aligned.m16n8k8.row.col.f32.tf32.tf32.f32 "
        "{%0,%1,%2,%3}, {%4,%5,%6,%7}, {%8,%9}, {%0,%1,%2,%3};"
        : "+f"(d[0]), "+f"(d[1]), "+f"(d[2]), "+f"(d[3])
        : "r"(a[0]), "r"(a[1]), "r"(a[2]), "r"(a[3]), "r"(b0), "r"(b1));
}

extern __shared__ float gm_smem[];

__global__ void __launch_bounds__(256, 3) gemm_mma_kernel(const float* __restrict__ W,
                                                          const float* __restrict__ bias,
                                                          float* __restrict__ out) {
    const float* A = g_vec;
    int tid = threadIdx.x;
    int wid = tid >> 5;
    int lane = tid & 31;
    int qr = lane >> 2;          // 0..7
    int c4 = lane & 3;           // 0..3
    int wm = wid & 3;            // warp row group (32 rows each)
    int wn = wid >> 2;           // warp col group (32 cols each)

    int n0 = blockIdx.x * 64;
    size_t m0 = (size_t)blockIdx.y * 128;

    // A loader: row = tid>>1 (0..127), half = tid&1 (16 floats = 4x cp16)
    int larow = tid >> 1;
    int lahalf = tid & 1;
    const float* asrc = A + (m0 + larow) * D_ + lahalf * 16;
    uint32_t smbase = smem_to_u32(gm_smem);
    uint32_t ldstA = smbase + (uint32_t)(larow * GS + lahalf * 16) * 4;
    // B loader: row = tid>>2 (0..63), seg = tid&3 (8 floats = 2x cp16)
    int lbrow = tid >> 2;
    int lbseg = tid & 3;
    int brow = n0 + lbrow;
    int bok = (brow < C_) ? 16 : 0;
    const float* bsrc = W + (size_t)(bok ? brow : 0) * D_ + lbseg * 8;
    uint32_t ldstB = smbase + (uint32_t)(A_ST + lbrow * GS + lbseg * 8) * 4;

    // prefetch stage 0
#pragma unroll
    for (int q = 0; q < 4; ++q) cp16(ldstA + q * 16, asrc + q * 4);
#pragma unroll
    for (int q = 0; q < 2; ++q) cp16z(ldstB + q * 16, bsrc + q * 4, bok);
    cp_commit();

    float acc[2][4][4];
#pragma unroll
    for (int mt = 0; mt < 2; ++mt)
#pragma unroll
        for (int nt = 0; nt < 4; ++nt)
#pragma unroll
            for (int u = 0; u < 4; ++u) acc[mt][nt][u] = 0.f;

    cp_wait0();
    __syncthreads();

    for (int bk = 0; bk < 8; ++bk) {
        int cur = bk & 1;
        if (bk < 7) {
            int nxt = cur ^ 1;
            uint32_t dA = ldstA + (uint32_t)(nxt * STAGE_F) * 4;
            uint32_t dB = ldstB + (uint32_t)(nxt * STAGE_F) * 4;
            const float* as = asrc + (bk + 1) * 32;
            const float* bs = bsrc + (bk + 1) * 32;
#pragma unroll
            for (int q = 0; q < 4; ++q) cp16(dA + q * 16, as + q * 4);
#pragma unroll
            for (int q = 0; q < 2; ++q) cp16z(dB + q * 16, bs + q * 4, bok);
            cp_commit();
        }

        const float* sA = gm_smem + cur * STAGE_F;
        const float* sB = sA + A_ST;
        int ra = wm * 32 + qr;
        int nb = wn * 32 + qr;
#pragma unroll
        for (int s = 0; s < 4; ++s) {
            int kb = 8 * s + c4;
            uint32_t af[2][4];
#pragma unroll
            for (int mt = 0; mt < 2; ++mt) {
                int r0 = ra + mt * 16;
                af[mt][0] = __float_as_uint(sA[r0 * GS + kb]);
                af[mt][1] = __float_as_uint(sA[(r0 + 8) * GS + kb]);
                af[mt][2] = __float_as_uint(sA[r0 * GS + kb + 4]);
                af[mt][3] = __float_as_uint(sA[(r0 + 8) * GS + kb + 4]);
            }
#pragma unroll
            for (int nt = 0; nt < 4; ++nt) {
                int n = nb + nt * 8;
                uint32_t b0 = __float_as_uint(sB[n * GS + kb]);
                uint32_t b1 = __float_as_uint(sB[n * GS + kb + 4]);
                mma_tf32(acc[0][nt], af[0], b0, b1);
                mma_tf32(acc[1][nt], af[1], b0, b1);
            }
        }

        if (bk < 7) cp_wait0();
        __syncthreads();
    }

    // epilogue: direct stores with bias
#pragma unroll
    for (int nt = 0; nt < 4; ++nt) {
        int col = n0 + wn * 32 + nt * 8 + 2 * c4;
        if (col >= C_) continue;
        bool c1ok = (col + 1) < C_;
        float b0v = bias[col];
        float b1v = c1ok ? bias[col + 1] : 0.f;
#pragma unroll
        for (int mt = 0; mt < 2; ++mt) {
            size_t m = m0 + wm * 32 + mt * 16 + qr;
            float* o0 = out + m * C_ + col;
            o0[0] = acc[mt][nt][0] + b0v;
            if (c1ok) o0[1] = acc[mt][nt][1] + b1v;
            float* o1 = out + (m + 8) * C_ + col;
            o1[0] = acc[mt][nt][2] + b0v;
            if (c1ok) o1[1] = acc[mt][nt][3] + b1v;
        }
    }
}

// ---------------------------------------------------------------------------
extern "C" void kernel_launch(void* const* d_in, const int* in_sizes, int n_in,
                              void* d_out, int out_size) {
    const int*   leaf_id = (const int*)d_in[1];    // (B,L,2) int32
    const int*   mask    = (const int*)d_in[2];    // (B,L)   int32
    const int*   comp    = (const int*)d_in[3];    // (B,T,4) int32
    const float* emb     = (const float*)d_in[4];  // (V,D)
    const float* W       = (const float*)d_in[5];  // (C,D)
    const float* bias    = (const float*)d_in[6];  // (C,)
    float* out = (float*)d_out;                    // (B,N,C)

    zero_kernel<<<2048, 256>>>();
    embed_kernel<<<(B_ * L_ + 7) / 8, 256>>>(leaf_id, mask, emb);
    compose_kernel<<<B_, 256>>>(comp);

    static bool attr_set = false;
    if (!attr_set) {
        cudaFuncSetAttribute(gemm_mma_kernel,
                             cudaFuncAttributeMaxDynamicSharedMemorySize,
                             2 * STAGE_F * 4);
        attr_set = true;
    }
    dim3 grid(8, 1023);   // x = n-tile fastest (A tile L2 reuse), y = m-tile
    gemm_mma_kernel<<<grid, 256, 2 * STAGE_F * 4>>>(W, bias, out);
}

// round 7
// speedup vs baseline: 1.0408x; 1.0408x over previous
#include <cuda_runtime.h>
#include <math.h>
#include <stdint.h>

#define B_ 128
#define L_ 512
#define N_ 1023
#define T_ 511
#define D_ 256
#define C_ 511
#define EPS_ 1e-6f

// 128*1023*256 floats = 134 MB scratch (allocs are forbidden -> device global)
__device__ float g_vec[(size_t)B_ * N_ * D_];

__device__ __forceinline__ uint32_t smem_to_u32(const void* p) {
    uint32_t a;
    asm("{ .reg .u64 t; cvta.to.shared.u64 t, %1; cvt.u32.u64 %0, t; }"
        : "=r"(a) : "l"(p));
    return a;
}

// ---------------------------------------------------------------------------
// Zero the node-vector buffer
// ---------------------------------------------------------------------------
__global__ void zero_kernel() {
    size_t total4 = (size_t)B_ * N_ * D_ / 4;
    float4* p = reinterpret_cast<float4*>(g_vec);
    float4 z = make_float4(0.f, 0.f, 0.f, 0.f);
    for (size_t i = (size_t)blockIdx.x * blockDim.x + threadIdx.x; i < total4;
         i += (size_t)gridDim.x * blockDim.x)
        p[i] = z;
}

// ---------------------------------------------------------------------------
// Scatter normalized embedding rows into g_vec. One warp per leaf.
// ---------------------------------------------------------------------------
__global__ void embed_kernel(const int* __restrict__ leaf_id,
                             const int* __restrict__ mask,
                             const float* __restrict__ emb) {
    int leaf = blockIdx.x * 8 + (threadIdx.x >> 5);
    int lane = threadIdx.x & 31;
    if (leaf >= B_ * L_) return;
    if (mask[leaf] == 0) return;
    int b = leaf / L_;
    int node = leaf_id[2 * leaf + 0];
    int vid  = leaf_id[2 * leaf + 1];
    if ((unsigned)node >= (unsigned)N_) return;
    const float4* src = reinterpret_cast<const float4*>(emb + (size_t)vid * D_);
    float4 v0 = src[lane];
    float4 v1 = src[lane + 32];
    float ss = v0.x * v0.x + v0.y * v0.y + v0.z * v0.z + v0.w * v0.w
             + v1.x * v1.x + v1.y * v1.y + v1.z * v1.z + v1.w * v1.w;
#pragma unroll
    for (int o = 16; o > 0; o >>= 1) ss += __shfl_xor_sync(0xffffffffu, ss, o);
    float inv = 1.f / (sqrtf(ss) + EPS_);
    v0.x *= inv; v0.y *= inv; v0.z *= inv; v0.w *= inv;
    v1.x *= inv; v1.y *= inv; v1.z *= inv; v1.w *= inv;
    float4* dst = reinterpret_cast<float4*>(g_vec + ((size_t)b * N_ + node) * D_);
    dst[lane]      = v0;
    dst[lane + 32] = v1;
}

// ---------------------------------------------------------------------------
// Sequential tree composition (R5 version — known good). One block per batch.
// ---------------------------------------------------------------------------
__global__ void __launch_bounds__(256) compose_kernel(const int* __restrict__ comp) {
    __shared__ int sinfo[T_ * 4];
    __shared__ __align__(16) float sa[D_];
    __shared__ float sbw[648];
    __shared__ float pt[4][320];
    __shared__ float red[8];

    int b = blockIdx.x;
    int tid = threadIdx.x;
    float* v = g_vec + (size_t)b * N_ * D_;

    for (int i = tid; i < T_ * 4; i += 256)
        sinfo[i] = comp[(size_t)b * T_ * 4 + i];
    __syncthreads();

    const int t  = tid & 63;
    const int g  = tid >> 6;
    const int t4 = t * 4;
    const int j0 = g * 64;
    const int P0 = (j0 + t4) + ((j0 + t4) >> 2);
    const int ftid = tid + (tid >> 2);

    for (int ts = 0; ts < T_; ++ts) {
        int typ = sinfo[4 * ts + 0];
        int p   = sinfo[4 * ts + 1];
        int l   = sinfo[4 * ts + 2];
        int r   = sinfo[4 * ts + 3];
        if (typ == 1) {
            v[(size_t)p * D_ + tid] = v[(size_t)l * D_ + tid];
        } else if (typ == 2) {
            float av = v[(size_t)l * D_ + tid];
            float bv = v[(size_t)r * D_ + tid];
            sa[tid] = av;
            int i0 = tid;
            int i1 = tid + 256;
            sbw[i0 + (i0 >> 2)] = bv;
            sbw[i1 + (i1 >> 2)] = bv;
            __syncthreads();

            float w0 = sbw[P0 + 0];
            float w1 = sbw[P0 + 1];
            float w2 = sbw[P0 + 2];
            float w3 = sbw[P0 + 3];
            float a0 = 0.f, a1 = 0.f, a2 = 0.f, a3 = 0.f;
#pragma unroll
            for (int u = 0; u < 16; ++u) {
                float4 aq = *reinterpret_cast<const float4*>(&sa[j0 + 4 * u]);
                int Pu = P0 + 5 * (u + 1);
                a0 += aq.x * w0; a1 += aq.x * w1; a2 += aq.x * w2; a3 += aq.x * w3;
                float n0v = sbw[Pu + 0];
                a0 += aq.y * w1; a1 += aq.y * w2; a2 += aq.y * w3; a3 += aq.y * n0v;
                float n1v = sbw[Pu + 1];
                a0 += aq.z * w2; a1 += aq.z * w3; a2 += aq.z * n0v; a3 += aq.z * n1v;
                float n2v = sbw[Pu + 2];
                a0 += aq.w * w3; a1 += aq.w * n0v; a2 += aq.w * n1v; a3 += aq.w * n2v;
                float n3v = sbw[Pu + 3];
                w0 = n0v; w1 = n1v; w2 = n2v; w3 = n3v;
            }
            pt[g][5 * t + 0] = a0;
            pt[g][5 * t + 1] = a1;
            pt[g][5 * t + 2] = a2;
            pt[g][5 * t + 3] = a3;
            __syncthreads();

            float tot = pt[0][ftid] + pt[1][ftid] + pt[2][ftid] + pt[3][ftid];
            float ss = tot * tot;
#pragma unroll
            for (int o = 16; o > 0; o >>= 1)
                ss += __shfl_xor_sync(0xffffffffu, ss, o);
            if ((tid & 31) == 0) red[tid >> 5] = ss;
            __syncthreads();
            float tss = red[0] + red[1] + red[2] + red[3]
                      + red[4] + red[5] + red[6] + red[7];
            v[(size_t)p * D_ + tid] = tot / (sqrtf(tss) + EPS_);
            __syncthreads();
        }
    }
}

// ---------------------------------------------------------------------------
// tf32 mma.sync GEMM: out[m, c] = sum_d A[m, d] * W[c, d] + bias[c]
// BM=128, BN=128, BK=32, 256 threads (8 warps: 4 along M x 2 along N).
// Warp tile 32x64 = 2 x 8 m16n8k8 tiles. 3-stage cp.async pipeline
// (prefetch distance 2, wait_group 1), stride-36 smem rows.
// ---------------------------------------------------------------------------
#define GS 36                      // smem row stride in floats
#define STAGE_F (2 * 128 * GS)     // 9216 floats = 36864 B per stage
#define NSTAGE 3

__device__ __forceinline__ void cp16(uint32_t dst, const void* src) {
    asm volatile("cp.async.ca.shared.global [%0], [%1], 16;"
                 :: "r"(dst), "l"(src) : "memory");
}
__device__ __forceinline__ void cp16z(uint32_t dst, const void* src, int srcsz) {
    asm volatile("cp.async.ca.shared.global [%0], [%1], 16, %2;"
                 :: "r"(dst), "l"(src), "r"(srcsz) : "memory");
}
__device__ __forceinline__ void cp_commit() {
    asm volatile("cp.async.commit_group;" ::: "memory");
}
__device__ __forceinline__ void cp_wait0() {
    asm volatile("cp.async.wait_group 0;" ::: "memory");
}
__device__ __forceinline__ void cp_wait1() {
    asm volatile("cp.async.wait_group 1;" ::: "memory");
}
__device__ __forceinline__ void mma_tf32(float* d, const uint32_t* a,
                                         uint32_t b0, uint32_t b1) {
    asm volatile(
        "mma.sync.aligned.m16n8k8.row.col.f32.tf32.tf32.f32 "
        "{%0,%1,%2,%3}, {%4,%5,%6,%7}, {%8,%9}, {%0,%1,%2,%3};"
        : "+f"(d[0]), "+f"(d[1]), "+f"(d[2]), "+f"(d[3])
        : "r"(a[0]), "r"(a[1]), "r"(a[2]), "r"(a[3]), "r"(b0), "r"(b1));
}

extern __shared__ float gm_smem[];

__global__ void __launch_bounds__(256, 2) gemm_mma_kernel(const float* __restrict__ W,
                                                          const float* __restrict__ bias,
                                                          float* __restrict__ out) {
    const float* A = g_vec;
    int tid = threadIdx.x;
    int wid = tid >> 5;
    int lane = tid & 31;
    int qr = lane >> 2;          // 0..7
    int c4 = lane & 3;           // 0..3
    int wm = wid & 3;            // warp row group (32 rows each)
    int wn = wid >> 2;           // warp col group (64 cols each)

    int n0 = blockIdx.x * 128;
    size_t m0 = (size_t)blockIdx.y * 128;

    // loader role: row = tid>>1 (0..127), half = tid&1 -> k offset half*16
    int lrow = tid >> 1;
    int lhalf = tid & 1;
    const float* asrc = A + (m0 + lrow) * D_ + lhalf * 16;
    int brow = n0 + lrow;
    int bok = (brow < C_) ? 16 : 0;
    const float* bsrc = W + (size_t)(bok ? brow : 0) * D_ + lhalf * 16;

    uint32_t smbase = smem_to_u32(gm_smem);
    uint32_t ldstA = smbase + (uint32_t)(lrow * GS + lhalf * 16) * 4;
    uint32_t ldstB = ldstA + 128 * GS * 4;

    // prefetch stages 0 and 1 (separate commit groups)
#pragma unroll
    for (int st = 0; st < 2; ++st) {
        uint32_t dA = ldstA + (uint32_t)(st * STAGE_F) * 4;
        uint32_t dB = ldstB + (uint32_t)(st * STAGE_F) * 4;
        const float* as = asrc + st * 32;
        const float* bs = bsrc + st * 32;
#pragma unroll
        for (int q = 0; q < 4; ++q) {
            cp16(dA + q * 16, as + q * 4);
            cp16z(dB + q * 16, bs + q * 4, bok);
        }
        cp_commit();
    }

    float acc[2][8][4];
#pragma unroll
    for (int mt = 0; mt < 2; ++mt)
#pragma unroll
        for (int nt = 0; nt < 8; ++nt)
#pragma unroll
            for (int u = 0; u < 4; ++u) acc[mt][nt][u] = 0.f;

    int slot = 0;
    for (int bk = 0; bk < 8; ++bk) {
        if (bk == 7) cp_wait0(); else cp_wait1();   // stage bk resident
        __syncthreads();                            // visible to all warps;
                                                    // also: all reads of the
                                                    // slot being overwritten
                                                    // below are complete

        if (bk < 6) {
            int wslot = slot + 2; if (wslot >= NSTAGE) wslot -= NSTAGE;
            uint32_t dA = ldstA + (uint32_t)(wslot * STAGE_F) * 4;
            uint32_t dB = ldstB + (uint32_t)(wslot * STAGE_F) * 4;
            const float* as = asrc + (bk + 2) * 32;
            const float* bs = bsrc + (bk + 2) * 32;
#pragma unroll
            for (int q = 0; q < 4; ++q) {
                cp16(dA + q * 16, as + q * 4);
                cp16z(dB + q * 16, bs + q * 4, bok);
            }
            cp_commit();
        }

        const float* sA = gm_smem + slot * STAGE_F;
        const float* sB = sA + 128 * GS;
        int ra = wm * 32 + qr;
        int nb = wn * 64 + qr;
#pragma unroll
        for (int s = 0; s < 4; ++s) {
            int kb = 8 * s + c4;
            uint32_t af[2][4];
#pragma unroll
            for (int mt = 0; mt < 2; ++mt) {
                int r0 = ra + mt * 16;
                af[mt][0] = __float_as_uint(sA[r0 * GS + kb]);
                af[mt][1] = __float_as_uint(sA[(r0 + 8) * GS + kb]);
                af[mt][2] = __float_as_uint(sA[r0 * GS + kb + 4]);
                af[mt][3] = __float_as_uint(sA[(r0 + 8) * GS + kb + 4]);
            }
#pragma unroll
            for (int nt = 0; nt < 8; ++nt) {
                int n = nb + nt * 8;
                uint32_t b0 = __float_as_uint(sB[n * GS + kb]);
                uint32_t b1 = __float_as_uint(sB[n * GS + kb + 4]);
                mma_tf32(acc[0][nt], af[0], b0, b1);
                mma_tf32(acc[1][nt], af[1], b0, b1);
            }
        }

        if (++slot >= NSTAGE) slot = 0;
    }

    // epilogue: direct stores with bias
#pragma unroll
    for (int nt = 0; nt < 8; ++nt) {
        int col = n0 + wn * 64 + nt * 8 + 2 * c4;
        if (col >= C_) continue;
        bool c1ok = (col + 1) < C_;
        float b0v = bias[col];
        float b1v = c1ok ? bias[col + 1] : 0.f;
#pragma unroll
        for (int mt = 0; mt < 2; ++mt) {
            size_t m = m0 + wm * 32 + mt * 16 + qr;
            float* o0 = out + m * C_ + col;
            o0[0] = acc[mt][nt][0] + b0v;
            if (c1ok) o0[1] = acc[mt][nt][1] + b1v;
            float* o1 = out + (m + 8) * C_ + col;
            o1[0] = acc[mt][nt][2] + b0v;
            if (c1ok) o1[1] = acc[mt][nt][3] + b1v;
        }
    }
}

// ---------------------------------------------------------------------------
extern "C" void kernel_launch(void* const* d_in, const int* in_sizes, int n_in,
                              void* d_out, int out_size) {
    const int*   leaf_id = (const int*)d_in[1];    // (B,L,2) int32
    const int*   mask    = (const int*)d_in[2];    // (B,L)   int32
    const int*   comp    = (const int*)d_in[3];    // (B,T,4) int32
    const float* emb     = (const float*)d_in[4];  // (V,D)
    const float* W       = (const float*)d_in[5];  // (C,D)
    const float* bias    = (const float*)d_in[6];  // (C,)
    float* out = (float*)d_out;                    // (B,N,C)

    zero_kernel<<<2048, 256>>>();
    embed_kernel<<<(B_ * L_ + 7) / 8, 256>>>(leaf_id, mask, emb);
    compose_kernel<<<B_, 256>>>(comp);

    static bool attr_set = false;
    if (!attr_set) {
        cudaFuncSetAttribute(gemm_mma_kernel,
                             cudaFuncAttributeMaxDynamicSharedMemorySize,
                             NSTAGE * STAGE_F * 4);
        attr_set = true;
    }
    dim3 grid(4, 1023);   // x = n-tile fastest (A tile L2 reuse), y = m-tile
    gemm_mma_kernel<<<grid, 256, NSTAGE * STAGE_F * 4>>>(W, bias, out);
}

// round 8
// speedup vs baseline: 1.1120x; 1.0684x over previous
#include <cuda_runtime.h>
#include <math.h>
#include <stdint.h>

#define B_ 128
#define L_ 512
#define N_ 1023
#define T_ 511
#define D_ 256
#define C_ 511
#define EPS_ 1e-6f

// 128*1023*256 floats = 134 MB scratch (allocs are forbidden -> device global)
__device__ float g_vec[(size_t)B_ * N_ * D_];

__device__ __forceinline__ uint32_t smem_to_u32(const void* p) {
    uint32_t a;
    asm("{ .reg .u64 t; cvta.to.shared.u64 t, %1; cvt.u32.u64 %0, t; }"
        : "=r"(a) : "l"(p));
    return a;
}

// ---------------------------------------------------------------------------
// Zero the node-vector buffer
// ---------------------------------------------------------------------------
__global__ void zero_kernel() {
    size_t total4 = (size_t)B_ * N_ * D_ / 4;
    float4* p = reinterpret_cast<float4*>(g_vec);
    float4 z = make_float4(0.f, 0.f, 0.f, 0.f);
    for (size_t i = (size_t)blockIdx.x * blockDim.x + threadIdx.x; i < total4;
         i += (size_t)gridDim.x * blockDim.x)
        p[i] = z;
}

// ---------------------------------------------------------------------------
// Scatter normalized embedding rows into g_vec. One warp per leaf.
// ---------------------------------------------------------------------------
__global__ void embed_kernel(const int* __restrict__ leaf_id,
                             const int* __restrict__ mask,
                             const float* __restrict__ emb) {
    int leaf = blockIdx.x * 8 + (threadIdx.x >> 5);
    int lane = threadIdx.x & 31;
    if (leaf >= B_ * L_) return;
    if (mask[leaf] == 0) return;
    int b = leaf / L_;
    int node = leaf_id[2 * leaf + 0];
    int vid  = leaf_id[2 * leaf + 1];
    if ((unsigned)node >= (unsigned)N_) return;
    const float4* src = reinterpret_cast<const float4*>(emb + (size_t)vid * D_);
    float4 v0 = src[lane];
    float4 v1 = src[lane + 32];
    float ss = v0.x * v0.x + v0.y * v0.y + v0.z * v0.z + v0.w * v0.w
             + v1.x * v1.x + v1.y * v1.y + v1.z * v1.z + v1.w * v1.w;
#pragma unroll
    for (int o = 16; o > 0; o >>= 1) ss += __shfl_xor_sync(0xffffffffu, ss, o);
    float inv = 1.f / (sqrtf(ss) + EPS_);
    v0.x *= inv; v0.y *= inv; v0.z *= inv; v0.w *= inv;
    v1.x *= inv; v1.y *= inv; v1.z *= inv; v1.w *= inv;
    float4* dst = reinterpret_cast<float4*>(g_vec + ((size_t)b * N_ + node) * D_);
    dst[lane]      = v0;
    dst[lane + 32] = v1;
}

// ---------------------------------------------------------------------------
// Sequential tree composition with cross-step operand prefetch.
// One block per batch. Step ts issues the LDGs for step ts+1 BEFORE its own
// compute; the only RAW hazard (next step reading the node just written) is
// patched in registers since g_vec column `tid` is private to thread `tid`.
// ---------------------------------------------------------------------------
__global__ void __launch_bounds__(256) compose_kernel(const int* __restrict__ comp) {
    __shared__ int sinfo[T_ * 4];
    __shared__ __align__(16) float sa[D_];
    __shared__ float sbw[648];
    __shared__ float pt[4][320];
    __shared__ float red[8];

    int b = blockIdx.x;
    int tid = threadIdx.x;
    float* v = g_vec + (size_t)b * N_ * D_;

    for (int i = tid; i < T_ * 4; i += 256)
        sinfo[i] = comp[(size_t)b * T_ * 4 + i];
    __syncthreads();

    const int t  = tid & 63;
    const int g  = tid >> 6;
    const int t4 = t * 4;
    const int j0 = g * 64;
    const int P0 = (j0 + t4) + ((j0 + t4) >> 2);
    const int ftid = tid + (tid >> 2);

    int typ = sinfo[0], p = sinfo[1], l = sinfo[2], r = sinfo[3];
    float av = v[(size_t)l * D_ + tid];
    float bv = v[(size_t)r * D_ + tid];

    for (int ts = 0; ts < T_; ++ts) {
        // ---- prefetch next step's operands (before this step's compute)
        int typ2 = 0, p2 = 0, l2 = 0, r2 = 0;
        float av2 = 0.f, bv2 = 0.f;
        if (ts + 1 < T_) {
            typ2 = sinfo[4 * ts + 4];
            p2   = sinfo[4 * ts + 5];
            l2   = sinfo[4 * ts + 6];
            r2   = sinfo[4 * ts + 7];
            av2 = v[(size_t)l2 * D_ + tid];
            bv2 = v[(size_t)r2 * D_ + tid];
        }

        float outv = 0.f;
        bool wrote = false;
        if (typ == 1) {
            outv = av;
            v[(size_t)p * D_ + tid] = outv;
            wrote = true;
        } else if (typ == 2) {
            sa[tid] = av;
            int i0 = tid;
            int i1 = tid + 256;
            sbw[i0 + (i0 >> 2)] = bv;
            sbw[i1 + (i1 >> 2)] = bv;
            __syncthreads();

            float w0 = sbw[P0 + 0];
            float w1 = sbw[P0 + 1];
            float w2 = sbw[P0 + 2];
            float w3 = sbw[P0 + 3];
            float a0 = 0.f, a1 = 0.f, a2 = 0.f, a3 = 0.f;
#pragma unroll
            for (int u = 0; u < 16; ++u) {
                float4 aq = *reinterpret_cast<const float4*>(&sa[j0 + 4 * u]);
                int Pu = P0 + 5 * (u + 1);
                a0 += aq.x * w0; a1 += aq.x * w1; a2 += aq.x * w2; a3 += aq.x * w3;
                float n0v = sbw[Pu + 0];
                a0 += aq.y * w1; a1 += aq.y * w2; a2 += aq.y * w3; a3 += aq.y * n0v;
                float n1v = sbw[Pu + 1];
                a0 += aq.z * w2; a1 += aq.z * w3; a2 += aq.z * n0v; a3 += aq.z * n1v;
                float n2v = sbw[Pu + 2];
                a0 += aq.w * w3; a1 += aq.w * n0v; a2 += aq.w * n1v; a3 += aq.w * n2v;
                float n3v = sbw[Pu + 3];
                w0 = n0v; w1 = n1v; w2 = n2v; w3 = n3v;
            }
            pt[g][5 * t + 0] = a0;
            pt[g][5 * t + 1] = a1;
            pt[g][5 * t + 2] = a2;
            pt[g][5 * t + 3] = a3;
            __syncthreads();

            float tot = pt[0][ftid] + pt[1][ftid] + pt[2][ftid] + pt[3][ftid];
            float ss = tot * tot;
#pragma unroll
            for (int o = 16; o > 0; o >>= 1)
                ss += __shfl_xor_sync(0xffffffffu, ss, o);
            if ((tid & 31) == 0) red[tid >> 5] = ss;
            __syncthreads();
            float tss = red[0] + red[1] + red[2] + red[3]
                      + red[4] + red[5] + red[6] + red[7];
            outv = tot / (sqrtf(tss) + EPS_);
            v[(size_t)p * D_ + tid] = outv;
            wrote = true;
            __syncthreads();   // protect sa/sbw/pt/red for next type-2 step
        }
        // typ == 0: exact no-op (reference writes v[b,0] back to itself)

        // ---- RAW hazard patch: next step reads the node we just wrote
        if (wrote && (ts + 1 < T_)) {
            if (l2 == p) av2 = outv;
            if (r2 == p) bv2 = outv;
        }
        typ = typ2; p = p2; l = l2; r = r2; av = av2; bv = bv2;
    }
}

// ---------------------------------------------------------------------------
// tf32 mma.sync GEMM (R5 configuration — best measured: 381us).
// BM=128, BN=128, BK=32, 256 threads (8 warps: 4 along M x 2 along N).
// Warp tile 32x64 = 2 x 8 m16n8k8 tiles. cp.async double-buffered smem,
// stride 36 floats (conflict-free frag LDS.32, 16B-aligned rows).
// ---------------------------------------------------------------------------
#define GS 36          // smem row stride in floats
#define STAGE_F (2 * 128 * GS)   // floats per stage (A tile + B tile)

__device__ __forceinline__ void cp16(uint32_t dst, const void* src) {
    asm volatile("cp.async.ca.shared.global [%0], [%1], 16;"
                 :: "r"(dst), "l"(src) : "memory");
}
__device__ __forceinline__ void cp16z(uint32_t dst, const void* src, int srcsz) {
    asm volatile("cp.async.ca.shared.global [%0], [%1], 16, %2;"
                 :: "r"(dst), "l"(src), "r"(srcsz) : "memory");
}
__device__ __forceinline__ void cp_commit() {
    asm volatile("cp.async.commit_group;" ::: "memory");
}
__device__ __forceinline__ void cp_wait0() {
    asm volatile("cp.async.wait_group 0;" ::: "memory");
}
__device__ __forceinline__ void mma_tf32(float* d, const uint32_t* a,
                                         uint32_t b0, uint32_t b1) {
    asm volatile(
        "mma.sync.aligned.m16n8k8.row.col.f32.tf32.tf32.f32 "
        "{%0,%1,%2,%3}, {%4,%5,%6,%7}, {%8,%9}, {%0,%1,%2,%3};"
        : "+f"(d[0]), "+f"(d[1]), "+f"(d[2]), "+f"(d[3])
        : "r"(a[0]), "r"(a[1]), "r"(a[2]), "r"(a[3]), "r"(b0), "r"(b1));
}

extern __shared__ float gm_smem[];

__global__ void __launch_bounds__(256, 2) gemm_mma_kernel(const float* __restrict__ W,
                                                          const float* __restrict__ bias,
                                                          float* __restrict__ out) {
    const float* A = g_vec;
    int tid = threadIdx.x;
    int wid = tid >> 5;
    int lane = tid & 31;
    int qr = lane >> 2;          // 0..7
    int c4 = lane & 3;           // 0..3
    int wm = wid & 3;            // warp row group (32 rows each)
    int wn = wid >> 2;           // warp col group (64 cols each)

    int n0 = blockIdx.x * 128;
    size_t m0 = (size_t)blockIdx.y * 128;

    // loader role: row = tid>>1 (0..127), half = tid&1 -> k offset half*16
    int lrow = tid >> 1;
    int lhalf = tid & 1;
    const float* asrc = A + (m0 + lrow) * D_ + lhalf * 16;
    int brow = n0 + lrow;
    int bok = (brow < C_) ? 16 : 0;
    const float* bsrc = W + (size_t)(bok ? brow : 0) * D_ + lhalf * 16;

    uint32_t smbase = smem_to_u32(gm_smem);
    uint32_t ldstA = smbase + (uint32_t)(lrow * GS + lhalf * 16) * 4;
    uint32_t ldstB = ldstA + 128 * GS * 4;

    // prefetch stage 0 (k0 = 0)
#pragma unroll
    for (int q = 0; q < 4; ++q) {
        cp16(ldstA + q * 16, asrc + q * 4);
        cp16z(ldstB + q * 16, bsrc + q * 4, bok);
    }
    cp_commit();

    float acc[2][8][4];
#pragma unroll
    for (int mt = 0; mt < 2; ++mt)
#pragma unroll
        for (int nt = 0; nt < 8; ++nt)
#pragma unroll
            for (int u = 0; u < 4; ++u) acc[mt][nt][u] = 0.f;

    cp_wait0();
    __syncthreads();

    for (int bk = 0; bk < 8; ++bk) {
        int cur = bk & 1;
        if (bk < 7) {
            int nxt = cur ^ 1;
            uint32_t dA = ldstA + (uint32_t)(nxt * STAGE_F) * 4;
            uint32_t dB = ldstB + (uint32_t)(nxt * STAGE_F) * 4;
            const float* as = asrc + (bk + 1) * 32;
            const float* bs = bsrc + (bk + 1) * 32;
#pragma unroll
            for (int q = 0; q < 4; ++q) {
                cp16(dA + q * 16, as + q * 4);
                cp16z(dB + q * 16, bs + q * 4, bok);
            }
            cp_commit();
        }

        const float* sA = gm_smem + cur * STAGE_F;
        const float* sB = sA + 128 * GS;
        int ra = wm * 32 + qr;
        int nb = wn * 64 + qr;
#pragma unroll
        for (int s = 0; s < 4; ++s) {
            int kb = 8 * s + c4;
            uint32_t af[2][4];
#pragma unroll
            for (int mt = 0; mt < 2; ++mt) {
                int r0 = ra + mt * 16;
                af[mt][0] = __float_as_uint(sA[r0 * GS + kb]);
                af[mt][1] = __float_as_uint(sA[(r0 + 8) * GS + kb]);
                af[mt][2] = __float_as_uint(sA[r0 * GS + kb + 4]);
                af[mt][3] = __float_as_uint(sA[(r0 + 8) * GS + kb + 4]);
            }
#pragma unroll
            for (int nt = 0; nt < 8; ++nt) {
                int n = nb + nt * 8;
                uint32_t b0 = __float_as_uint(sB[n * GS + kb]);
                uint32_t b1 = __float_as_uint(sB[n * GS + kb + 4]);
                mma_tf32(acc[0][nt], af[0], b0, b1);
                mma_tf32(acc[1][nt], af[1], b0, b1);
            }
        }

        if (bk < 7) cp_wait0();
        __syncthreads();
    }

    // epilogue: direct stores with bias
#pragma unroll
    for (int nt = 0; nt < 8; ++nt) {
        int col = n0 + wn * 64 + nt * 8 + 2 * c4;
        if (col >= C_) continue;
        bool c1ok = (col + 1) < C_;
        float b0v = bias[col];
        float b1v = c1ok ? bias[col + 1] : 0.f;
#pragma unroll
        for (int mt = 0; mt < 2; ++mt) {
            size_t m = m0 + wm * 32 + mt * 16 + qr;
            float* o0 = out + m * C_ + col;
            o0[0] = acc[mt][nt][0] + b0v;
            if (c1ok) o0[1] = acc[mt][nt][1] + b1v;
            float* o1 = out + (m + 8) * C_ + col;
            o1[0] = acc[mt][nt][2] + b0v;
            if (c1ok) o1[1] = acc[mt][nt][3] + b1v;
        }
    }
}

// ---------------------------------------------------------------------------
extern "C" void kernel_launch(void* const* d_in, const int* in_sizes, int n_in,
                              void* d_out, int out_size) {
    const int*   leaf_id = (const int*)d_in[1];    // (B,L,2) int32
    const int*   mask    = (const int*)d_in[2];    // (B,L)   int32
    const int*   comp    = (const int*)d_in[3];    // (B,T,4) int32
    const float* emb     = (const float*)d_in[4];  // (V,D)
    const float* W       = (const float*)d_in[5];  // (C,D)
    const float* bias    = (const float*)d_in[6];  // (C,)
    float* out = (float*)d_out;                    // (B,N,C)

    zero_kernel<<<2048, 256>>>();
    embed_kernel<<<(B_ * L_ + 7) / 8, 256>>>(leaf_id, mask, emb);
    compose_kernel<<<B_, 256>>>(comp);

    static bool attr_set = false;
    if (!attr_set) {
        cudaFuncSetAttribute(gemm_mma_kernel,
                             cudaFuncAttributeMaxDynamicSharedMemorySize,
                             2 * STAGE_F * 4);
        attr_set = true;
    }
    dim3 grid(4, 1023);   // x = n-tile fastest (A tile L2 reuse), y = m-tile
    gemm_mma_kernel<<<grid, 256, 2 * STAGE_F * 4>>>(W, bias, out);
}